// round 3
// baseline (speedup 1.0000x reference)
#include <cuda_runtime.h>
#include <math.h>

#define BATCH 64
#define TSTEPS 512
#define IDIM 1024
#define HDIM 1024
#define KSPLIT 4
#define KC (HDIM / KSPLIT)   // 256
#define BK 32
#define HC_TILE 32
#define NBLOCKS 128

// ---------------- scratch (static device allocations only) ----------------
__device__ float g_xproj[(size_t)TSTEPS * BATCH * 4 * HDIM]; // [T][B][4H]
__device__ float g_h[2][BATCH * HDIM];                       // ping-pong h
__device__ float g_c[BATCH * HDIM];                          // cell state
__device__ float g_part[(size_t)KSPLIT * BATCH * 4 * HDIM];  // [ks][b][g][hc]
__device__ unsigned g_bar;                                   // grid barrier counter

// ---------------- init: h0 = c0 = 0, barrier counter = 0 ----------------
__global__ void init_state() {
    int i = blockIdx.x * blockDim.x + threadIdx.x;
    if (i == 0) g_bar = 0;
    if (i < BATCH * HDIM) {
        g_h[0][i] = 0.0f;
        g_c[i]    = 0.0f;
    }
}

// ---------------- x-projection GEMM ----------------
// C[m, gate*H + n] = sum_k x[m,k] * Wg[k,n] + bias_g[n]
// stored time-major: g_xproj[(t*B + b)*4H + gate*H + n], m = b*T + t
__global__ __launch_bounds__(256) void xproj_kernel(
    const float* __restrict__ x,
    const float* __restrict__ W0, const float* __restrict__ W1,
    const float* __restrict__ W2, const float* __restrict__ W3,
    const float* __restrict__ bb0, const float* __restrict__ bb1,
    const float* __restrict__ bb2, const float* __restrict__ bb3)
{
    __shared__ float As[8][132];   // transposed A tile, padded
    __shared__ float Bs[8][128];

    int bx = blockIdx.x;           // 0..31 : gate = bx>>3, n-tile within gate
    int by = blockIdx.y;           // 0..255 : m tile
    int gate = bx >> 3;
    int n0 = (bx & 7) << 7;        // col offset within gate [0,1024)
    const float* W    = (gate == 0) ? W0  : (gate == 1) ? W1  : (gate == 2) ? W2  : W3;
    const float* bias = (gate == 0) ? bb0 : (gate == 1) ? bb1 : (gate == 2) ? bb2 : bb3;

    int tid = threadIdx.x;
    int tx = tid & 15;             // 0..15
    int ty = tid >> 4;             // 0..15
    int m0 = by << 7;

    int arow = tid >> 1;           // 0..127
    int acol = (tid & 1) << 2;     // 0 or 4
    int brow = tid >> 5;           // 0..7
    int bcol = (tid & 31) << 2;    // 0..124

    const float* aptr = x + (size_t)(m0 + arow) * IDIM + acol;
    const float* bptr = W + (size_t)brow * HDIM + n0 + bcol;

    float acc[8][8];
#pragma unroll
    for (int i = 0; i < 8; i++)
#pragma unroll
        for (int j = 0; j < 8; j++) acc[i][j] = 0.0f;

    for (int k0 = 0; k0 < IDIM; k0 += 8) {
        float4 av = *(const float4*)(aptr + k0);
        float4 bv = *(const float4*)(bptr + (size_t)k0 * HDIM);
        As[acol + 0][arow] = av.x;
        As[acol + 1][arow] = av.y;
        As[acol + 2][arow] = av.z;
        As[acol + 3][arow] = av.w;
        *(float4*)&Bs[brow][bcol] = bv;
        __syncthreads();

#pragma unroll
        for (int kk = 0; kk < 8; kk++) {
            float4 a0 = *(const float4*)&As[kk][ty * 4];
            float4 a1 = *(const float4*)&As[kk][64 + ty * 4];
            float4 b0 = *(const float4*)&Bs[kk][tx * 4];
            float4 b1 = *(const float4*)&Bs[kk][64 + tx * 4];
            float a[8] = {a0.x, a0.y, a0.z, a0.w, a1.x, a1.y, a1.z, a1.w};
            float b[8] = {b0.x, b0.y, b0.z, b0.w, b1.x, b1.y, b1.z, b1.w};
#pragma unroll
            for (int i = 0; i < 8; i++)
#pragma unroll
                for (int j = 0; j < 8; j++) acc[i][j] += a[i] * b[j];
        }
        __syncthreads();
    }

    float biasv[8];
#pragma unroll
    for (int j = 0; j < 4; j++) {
        biasv[j]     = bias[n0 + tx * 4 + j];
        biasv[4 + j] = bias[n0 + 64 + tx * 4 + j];
    }

#pragma unroll
    for (int i = 0; i < 8; i++) {
        int r = m0 + ((i < 4) ? (ty * 4 + i) : (64 + ty * 4 + (i - 4)));
        int b = r >> 9;       // batch (T = 512)
        int t = r & 511;      // timestep
        float* orow = g_xproj + ((size_t)t * BATCH + b) * 4 * HDIM + (size_t)gate * HDIM + n0;
        float4 o0 = make_float4(acc[i][0] + biasv[0], acc[i][1] + biasv[1],
                                acc[i][2] + biasv[2], acc[i][3] + biasv[3]);
        float4 o1 = make_float4(acc[i][4] + biasv[4], acc[i][5] + biasv[5],
                                acc[i][6] + biasv[6], acc[i][7] + biasv[7]);
        *(float4*)(orow + tx * 4)      = o0;
        *(float4*)(orow + 64 + tx * 4) = o1;
    }
}

// ---------------- grid barrier (monotonic counter, reset per replay) ------
__device__ __forceinline__ void grid_barrier(unsigned target) {
    __syncthreads();
    if (threadIdx.x == 0) {
        __threadfence();                       // release my writes
        atomicAdd(&g_bar, 1u);
        volatile unsigned* p = &g_bar;
        while (*p < target) { __nanosleep(64); }
        __threadfence();                       // acquire others' writes
    }
    __syncthreads();
}

// ---------------- persistent recurrence kernel ----------------
// 128 blocks x 256 threads, all co-resident (1 block/SM max).
// Per step: phase1 = partial GEMM h @ Wh (same tiling as before),
//           barrier, phase2 = reduce partials + gate math, barrier.
__global__ __launch_bounds__(256, 1) void lstm_persistent(
    const float* __restrict__ W0, const float* __restrict__ W1,
    const float* __restrict__ W2, const float* __restrict__ W3,
    float* __restrict__ out)
{
    __shared__ float As[BK][68];       // transposed h tile, padded
    __shared__ float Bs[4][BK][36];    // per-gate Wh tile, padded

    const int tid = threadIdx.x;
    const int hc0 = (blockIdx.x & 31) * HC_TILE;   // hc tile
    const int ksb = blockIdx.x >> 5;               // k-split index 0..3
    const int k0  = ksb * KC;
    const int cp  = tid & 15;    // col pair -> hcols {hc0+2cp, +1}
    const int rg  = tid >> 4;    // 0..15
    const int r0  = rg * 4;      // rows r0..r0+3

    const float* Wp[4] = {W0, W1, W2, W3};

    // phase2 indices: each thread owns one float2 of the 64x1024 state
    const int idx2 = ((int)blockIdx.x * 256 + tid) * 2;   // 0..65534, even
    const int p2b  = idx2 >> 10;
    const int p2hc = idx2 & (HDIM - 1);

    unsigned bar_epoch = 0;

    for (int t = 0; t < TSTEPS; t++) {
        // ---------- phase 1: partial GEMM ----------
        const float* h_in = g_h[t & 1];

        float acc[4][2][4];
#pragma unroll
        for (int g = 0; g < 4; g++)
#pragma unroll
            for (int j = 0; j < 2; j++)
#pragma unroll
                for (int i = 0; i < 4; i++) acc[g][j][i] = 0.0f;

        for (int kt = 0; kt < KC; kt += BK) {
            int kbase = k0 + kt;
#pragma unroll
            for (int q = 0; q < 2; q++) {
                int v   = tid + q * 256;
                int row = v >> 3;
                int kk  = (v & 7) << 2;
                float4 av = *(const float4*)(h_in + (size_t)row * HDIM + kbase + kk);
                As[kk + 0][row] = av.x;
                As[kk + 1][row] = av.y;
                As[kk + 2][row] = av.z;
                As[kk + 3][row] = av.w;
            }
            {
                int kk = tid >> 3;
                int c4 = (tid & 7) << 2;
#pragma unroll
                for (int g = 0; g < 4; g++) {
                    float4 bv = *(const float4*)(Wp[g] + (size_t)(kbase + kk) * HDIM + hc0 + c4);
                    Bs[g][kk][c4 + 0] = bv.x;
                    Bs[g][kk][c4 + 1] = bv.y;
                    Bs[g][kk][c4 + 2] = bv.z;
                    Bs[g][kk][c4 + 3] = bv.w;
                }
            }
            __syncthreads();

#pragma unroll
            for (int kk = 0; kk < BK; kk++) {
                float4 a = *(const float4*)&As[kk][r0];
#pragma unroll
                for (int g = 0; g < 4; g++) {
                    float2 b = *(const float2*)&Bs[g][kk][cp * 2];
                    acc[g][0][0] += a.x * b.x;
                    acc[g][0][1] += a.y * b.x;
                    acc[g][0][2] += a.z * b.x;
                    acc[g][0][3] += a.w * b.x;
                    acc[g][1][0] += a.x * b.y;
                    acc[g][1][1] += a.y * b.y;
                    acc[g][1][2] += a.z * b.y;
                    acc[g][1][3] += a.w * b.y;
                }
            }
            __syncthreads();
        }

#pragma unroll
        for (int g = 0; g < 4; g++)
#pragma unroll
            for (int i = 0; i < 4; i++) {
                int row = r0 + i;
                float2 val = make_float2(acc[g][0][i], acc[g][1][i]);
                *(float2*)(g_part + (((size_t)ksb * BATCH + row) * 4 + g) * HDIM
                           + hc0 + cp * 2) = val;
            }

        grid_barrier(++bar_epoch * NBLOCKS);

        // ---------- phase 2: reduce partials + gate update ----------
        {
            const float* xp = g_xproj + ((size_t)t * BATCH + p2b) * 4 * HDIM;
            float2 v[4];
#pragma unroll
            for (int g = 0; g < 4; g++)
                v[g] = *(const float2*)(xp + (size_t)g * HDIM + p2hc);
#pragma unroll
            for (int ks = 0; ks < KSPLIT; ks++)
#pragma unroll
                for (int g = 0; g < 4; g++) {
                    float2 pv = *(const float2*)(g_part +
                        (((size_t)ks * BATCH + p2b) * 4 + g) * HDIM + p2hc);
                    v[g].x += pv.x;
                    v[g].y += pv.y;
                }

            float2 cold = *(const float2*)(g_c + idx2);
            float2 hnew, cnew;
            {
                float i_t = 1.0f / (1.0f + expf(-v[0].x));
                float f_t = 1.0f / (1.0f + expf(-v[1].x));
                float gg  = tanhf(v[2].x);
                float o_t = 1.0f / (1.0f + expf(-v[3].x));
                cnew.x = f_t * cold.x + i_t * gg;
                hnew.x = o_t * tanhf(cnew.x);
            }
            {
                float i_t = 1.0f / (1.0f + expf(-v[0].y));
                float f_t = 1.0f / (1.0f + expf(-v[1].y));
                float gg  = tanhf(v[2].y);
                float o_t = 1.0f / (1.0f + expf(-v[3].y));
                cnew.y = f_t * cold.y + i_t * gg;
                hnew.y = o_t * tanhf(cnew.y);
            }

            *(float2*)(g_c + idx2) = cnew;
            if (t == TSTEPS - 1) {
                *(float2*)(out + idx2) = hnew;                    // h_T
                *(float2*)(out + BATCH * HDIM + idx2) = cnew;     // c_T
            } else {
                *(float2*)(&g_h[(t + 1) & 1][idx2]) = hnew;
            }
        }

        if (t != TSTEPS - 1)
            grid_barrier(++bar_epoch * NBLOCKS);
    }
}

// ---------------- launch ----------------
extern "C" void kernel_launch(void* const* d_in, const int* in_sizes, int n_in,
                              void* d_out, int out_size)
{
    const float* x    = (const float*)d_in[0];
    const float* Wii  = (const float*)d_in[1];
    const float* Whi  = (const float*)d_in[2];
    const float* b_hi = (const float*)d_in[3];
    const float* Wif  = (const float*)d_in[4];
    const float* Whf  = (const float*)d_in[5];
    const float* b_hf = (const float*)d_in[6];
    const float* Wig  = (const float*)d_in[7];
    const float* Whg  = (const float*)d_in[8];
    const float* b_hg = (const float*)d_in[9];
    const float* Wio  = (const float*)d_in[10];
    const float* Who  = (const float*)d_in[11];
    const float* b_ho = (const float*)d_in[12];
    float* out = (float*)d_out;

    init_state<<<(BATCH * HDIM + 255) / 256, 256>>>();

    dim3 gx(32, 256);
    xproj_kernel<<<gx, 256>>>(x, Wii, Wif, Wig, Wio, b_hi, b_hf, b_hg, b_ho);

    lstm_persistent<<<NBLOCKS, 256>>>(Whi, Whf, Whg, Who, out);
}

// round 4
// speedup vs baseline: 1.2356x; 1.2356x over previous
#include <cuda_runtime.h>
#include <cuda_bf16.h>
#include <math.h>
#include <stdint.h>

#define BATCH 64
#define TSTEPS 512
#define IDIM 1024
#define HDIM 1024
#define KSPLIT 4
#define KC (HDIM / KSPLIT)   // 256
#define BK 32
#define HC_TILE 32
#define NBLOCKS 128

// ---------------- scratch (static device allocations only) ----------------
__device__ float g_xproj[(size_t)TSTEPS * BATCH * 4 * HDIM]; // [T][B][4H]
__device__ float g_h[2][BATCH * HDIM];
__device__ float g_c[BATCH * HDIM];
__device__ float g_part[(size_t)KSPLIT * BATCH * 4 * HDIM];
__device__ unsigned g_bar;

// bf16 split operands for tensor-core xproj
__device__ __nv_bfloat16 g_xhi[(size_t)BATCH * TSTEPS * IDIM];   // 33.5M
__device__ __nv_bfloat16 g_xlo[(size_t)BATCH * TSTEPS * IDIM];
__device__ __nv_bfloat16 g_wxhi[(size_t)IDIM * 4 * HDIM];        // [K][4096]
__device__ __nv_bfloat16 g_wxlo[(size_t)IDIM * 4 * HDIM];
__device__ float g_bx[4 * HDIM];

// ---------------- init ----------------
__global__ void init_state() {
    int i = blockIdx.x * blockDim.x + threadIdx.x;
    if (i == 0) g_bar = 0;
    if (i < BATCH * HDIM) {
        g_h[0][i] = 0.0f;
        g_c[i]    = 0.0f;
    }
}

// ---------------- bf16 hi/lo split kernels ----------------
__global__ __launch_bounds__(256) void split_x(const float* __restrict__ x) {
    size_t i = (size_t)blockIdx.x * blockDim.x + threadIdx.x;   // per 2 elems
    float2 v = ((const float2*)x)[i];
    __nv_bfloat16 h0 = __float2bfloat16(v.x);
    __nv_bfloat16 h1 = __float2bfloat16(v.y);
    __nv_bfloat16 l0 = __float2bfloat16(v.x - __bfloat162float(h0));
    __nv_bfloat16 l1 = __float2bfloat16(v.y - __bfloat162float(h1));
    __nv_bfloat162 hp; hp.x = h0; hp.y = h1;
    __nv_bfloat162 lp; lp.x = l0; lp.y = l1;
    ((__nv_bfloat162*)g_xhi)[i] = hp;
    ((__nv_bfloat162*)g_xlo)[i] = lp;
}

__global__ __launch_bounds__(256) void split_w(
    const float* __restrict__ W0, const float* __restrict__ W1,
    const float* __restrict__ W2, const float* __restrict__ W3)
{
    size_t i = (size_t)blockIdx.x * blockDim.x + threadIdx.x;   // per 2 elems
    size_t n2 = i * 2;
    int k = (int)(n2 >> 12);
    int n = (int)(n2 & 4095);
    int gate = n >> 10;
    int col = n & 1023;
    const float* W = (gate == 0) ? W0 : (gate == 1) ? W1 : (gate == 2) ? W2 : W3;
    float2 v = *(const float2*)(W + (size_t)k * HDIM + col);
    __nv_bfloat16 h0 = __float2bfloat16(v.x);
    __nv_bfloat16 h1 = __float2bfloat16(v.y);
    __nv_bfloat16 l0 = __float2bfloat16(v.x - __bfloat162float(h0));
    __nv_bfloat16 l1 = __float2bfloat16(v.y - __bfloat162float(h1));
    __nv_bfloat162 hp; hp.x = h0; hp.y = h1;
    __nv_bfloat162 lp; lp.x = l0; lp.y = l1;
    ((__nv_bfloat162*)g_wxhi)[i] = hp;
    ((__nv_bfloat162*)g_wxlo)[i] = lp;
}

__global__ void concat_bias(
    const float* __restrict__ b0, const float* __restrict__ b1,
    const float* __restrict__ b2, const float* __restrict__ b3)
{
    int i = blockIdx.x * blockDim.x + threadIdx.x;
    if (i < 4 * HDIM) {
        int gate = i >> 10;
        const float* b = (gate == 0) ? b0 : (gate == 1) ? b1 : (gate == 2) ? b2 : b3;
        g_bx[i] = b[i & 1023];
    }
}

// ---------------- tensor-core x-projection ----------------
// C[m, n] = sum_k x[m,k]*Wx[k,n] (+ bias), m = b*T+t, n in [0,4096)
// stored g_xproj[(t*B + b)*4096 + n].
// Block 128x256, BK=32, 8 warps (2m x 4n), warp tile 64x64.
// 3-pass bf16: hi*hi + hi*lo + lo*hi.

#define XP_SAS_B 80      // A smem row stride bytes (32 halves + pad)
#define XP_SBS_B 528     // B smem row stride bytes (256 halves + pad)
#define XP_A_BUF 10240   // 128 * 80
#define XP_B_BUF 16896   // 32 * 528
#define XP_A_OFF(st, hl) ((st) * 20480 + (hl) * XP_A_BUF)
#define XP_B_OFF(st, hl) (40960 + (st) * 33792 + (hl) * XP_B_BUF)
#define XP_SMEM_TOTAL 108544

#define CP_ASYNC16(dst_u32, src_ptr) \
    asm volatile("cp.async.cg.shared.global [%0], [%1], 16;" :: "r"(dst_u32), "l"(src_ptr))
#define CP_COMMIT() asm volatile("cp.async.commit_group;")

#define LDSM4(R, addr) \
    asm volatile("ldmatrix.sync.aligned.m8n8.x4.shared.b16 {%0,%1,%2,%3}, [%4];" \
        : "=r"((R)[0]), "=r"((R)[1]), "=r"((R)[2]), "=r"((R)[3]) : "r"(addr))
#define LDSM4T(R, addr) \
    asm volatile("ldmatrix.sync.aligned.m8n8.x4.trans.shared.b16 {%0,%1,%2,%3}, [%4];" \
        : "=r"((R)[0]), "=r"((R)[1]), "=r"((R)[2]), "=r"((R)[3]) : "r"(addr))

#define MMA_BF16(C, A, B0, B1) \
    asm volatile("mma.sync.aligned.m16n8k16.row.col.f32.bf16.bf16.f32 " \
        "{%0,%1,%2,%3}, {%4,%5,%6,%7}, {%8,%9}, {%0,%1,%2,%3};" \
        : "+f"((C)[0]), "+f"((C)[1]), "+f"((C)[2]), "+f"((C)[3]) \
        : "r"((A)[0]), "r"((A)[1]), "r"((A)[2]), "r"((A)[3]), "r"(B0), "r"(B1))

__global__ __launch_bounds__(256) void xproj_tc()
{
    extern __shared__ __align__(16) char xsm[];
    uint32_t smemu = (uint32_t)__cvta_generic_to_shared(xsm);

    const int tid  = threadIdx.x;
    const int wid  = tid >> 5;
    const int lane = tid & 31;
    const int wm64 = (wid & 1) * 64;
    const int wn64 = (wid >> 1) * 64;
    const int m0 = blockIdx.x * 128;
    const int n0 = blockIdx.y * 256;

    // cp.async chunk assignments
    // A: idx = tid + j*256, j<4 : hl = idx>>9, rem=idx&511, row=rem>>2, c=rem&3
    // B: idx = tid + j*256, j<8 : hl = idx>>10, rem=idx&1023, row=rem>>5, c=rem&31
    float acc[4][8][4];
#pragma unroll
    for (int mt = 0; mt < 4; mt++)
#pragma unroll
        for (int nt = 0; nt < 8; nt++)
#pragma unroll
            for (int q = 0; q < 4; q++) acc[mt][nt][q] = 0.0f;

    const int NKB = IDIM / BK;   // 32

    // ---- issue stage for kb ----
    auto issue = [&](int kb) {
        int st = kb & 1;
        int k0 = kb * BK;
#pragma unroll
        for (int j = 0; j < 4; j++) {
            int idx = tid + j * 256;
            int hl  = idx >> 9;
            int rem = idx & 511;
            int row = rem >> 2;
            int c   = rem & 3;
            const __nv_bfloat16* src = (hl ? g_xlo : g_xhi)
                + (size_t)(m0 + row) * IDIM + k0 + c * 8;
            uint32_t dst = smemu + XP_A_OFF(st, hl) + row * XP_SAS_B + c * 16;
            CP_ASYNC16(dst, src);
        }
#pragma unroll
        for (int j = 0; j < 8; j++) {
            int idx = tid + j * 256;
            int hl  = idx >> 10;
            int rem = idx & 1023;
            int row = rem >> 5;
            int c   = rem & 31;
            const __nv_bfloat16* src = (hl ? g_wxlo : g_wxhi)
                + (size_t)(k0 + row) * 4096 + n0 + c * 8;
            uint32_t dst = smemu + XP_B_OFF(st, hl) + row * XP_SBS_B + c * 16;
            CP_ASYNC16(dst, src);
        }
        CP_COMMIT();
    };

    issue(0);

    const int lrow  = lane & 15;
    const int lhalf = lane >> 4;
    const int brow  = (lane & 7) + ((lane >> 3) & 1) * 8;
    const int bcolo = (lane >> 4) * 8;

    for (int kb = 0; kb < NKB; kb++) {
        if (kb + 1 < NKB) issue(kb + 1);
        if (kb + 1 < NKB) asm volatile("cp.async.wait_group 1;");
        else              asm volatile("cp.async.wait_group 0;");
        __syncthreads();

        int st = kb & 1;
#pragma unroll
        for (int kstep = 0; kstep < 2; kstep++) {
            uint32_t ah[4][4], al[4][4], bh[4][4], bl[4][4];
#pragma unroll
            for (int mt = 0; mt < 4; mt++) {
                uint32_t base = smemu + (wm64 + mt * 16 + lrow) * XP_SAS_B
                              + lhalf * 16 + kstep * 32;
                LDSM4(ah[mt], base + XP_A_OFF(st, 0));
                LDSM4(al[mt], base + XP_A_OFF(st, 1));
            }
#pragma unroll
            for (int nt2 = 0; nt2 < 4; nt2++) {
                uint32_t base = smemu + (kstep * 16 + brow) * XP_SBS_B
                              + (wn64 + nt2 * 16 + bcolo) * 2;
                LDSM4T(bh[nt2], base + XP_B_OFF(st, 0));
                LDSM4T(bl[nt2], base + XP_B_OFF(st, 1));
            }
#pragma unroll
            for (int mt = 0; mt < 4; mt++)
#pragma unroll
                for (int nt = 0; nt < 8; nt++) {
                    int p = nt >> 1, q = (nt & 1) * 2;
                    MMA_BF16(acc[mt][nt], ah[mt], bh[p][q], bh[p][q + 1]);
                    MMA_BF16(acc[mt][nt], ah[mt], bl[p][q], bl[p][q + 1]);
                    MMA_BF16(acc[mt][nt], al[mt], bh[p][q], bh[p][q + 1]);
                }
        }
        __syncthreads();
    }

    // ---- epilogue: scatter to g_xproj (time-major) + bias ----
    const int g  = lane >> 2;
    const int tg = lane & 3;
#pragma unroll
    for (int mt = 0; mt < 4; mt++) {
        int row0 = m0 + wm64 + mt * 16 + g;
        int row1 = row0 + 8;
        int b0 = row0 >> 9, t0 = row0 & 511;
        int b1 = row1 >> 9, t1 = row1 & 511;
        float* dst0 = g_xproj + ((size_t)(t0 * BATCH + b0) << 12);
        float* dst1 = g_xproj + ((size_t)(t1 * BATCH + b1) << 12);
#pragma unroll
        for (int nt = 0; nt < 8; nt++) {
            int nglob = n0 + wn64 + nt * 8 + tg * 2;
            float2 bias = *(const float2*)(g_bx + nglob);
            float2 o0 = make_float2(acc[mt][nt][0] + bias.x, acc[mt][nt][1] + bias.y);
            float2 o1 = make_float2(acc[mt][nt][2] + bias.x, acc[mt][nt][3] + bias.y);
            *(float2*)(dst0 + nglob) = o0;
            *(float2*)(dst1 + nglob) = o1;
        }
    }
}

// ---------------- grid barrier ----------------
__device__ __forceinline__ void grid_barrier(unsigned target) {
    __syncthreads();
    if (threadIdx.x == 0) {
        __threadfence();
        atomicAdd(&g_bar, 1u);
        volatile unsigned* p = &g_bar;
        while (*p < target) { __nanosleep(64); }
        __threadfence();
    }
    __syncthreads();
}

// ---------------- persistent recurrence kernel (fp32, unchanged) ----------
__global__ __launch_bounds__(256, 1) void lstm_persistent(
    const float* __restrict__ W0, const float* __restrict__ W1,
    const float* __restrict__ W2, const float* __restrict__ W3,
    float* __restrict__ out)
{
    __shared__ float As[BK][68];
    __shared__ float Bs[4][BK][36];

    const int tid = threadIdx.x;
    const int hc0 = (blockIdx.x & 31) * HC_TILE;
    const int ksb = blockIdx.x >> 5;
    const int k0  = ksb * KC;
    const int cp  = tid & 15;
    const int rg  = tid >> 4;
    const int r0  = rg * 4;

    const float* Wp[4] = {W0, W1, W2, W3};

    const int idx2 = ((int)blockIdx.x * 256 + tid) * 2;
    const int p2b  = idx2 >> 10;
    const int p2hc = idx2 & (HDIM - 1);

    unsigned bar_epoch = 0;

    for (int t = 0; t < TSTEPS; t++) {
        const float* h_in = g_h[t & 1];

        float acc[4][2][4];
#pragma unroll
        for (int g = 0; g < 4; g++)
#pragma unroll
            for (int j = 0; j < 2; j++)
#pragma unroll
                for (int i = 0; i < 4; i++) acc[g][j][i] = 0.0f;

        for (int kt = 0; kt < KC; kt += BK) {
            int kbase = k0 + kt;
#pragma unroll
            for (int q = 0; q < 2; q++) {
                int v   = tid + q * 256;
                int row = v >> 3;
                int kk  = (v & 7) << 2;
                float4 av = *(const float4*)(h_in + (size_t)row * HDIM + kbase + kk);
                As[kk + 0][row] = av.x;
                As[kk + 1][row] = av.y;
                As[kk + 2][row] = av.z;
                As[kk + 3][row] = av.w;
            }
            {
                int kk = tid >> 3;
                int c4 = (tid & 7) << 2;
#pragma unroll
                for (int g = 0; g < 4; g++) {
                    float4 bv = *(const float4*)(Wp[g] + (size_t)(kbase + kk) * HDIM + hc0 + c4);
                    Bs[g][kk][c4 + 0] = bv.x;
                    Bs[g][kk][c4 + 1] = bv.y;
                    Bs[g][kk][c4 + 2] = bv.z;
                    Bs[g][kk][c4 + 3] = bv.w;
                }
            }
            __syncthreads();

#pragma unroll
            for (int kk = 0; kk < BK; kk++) {
                float4 a = *(const float4*)&As[kk][r0];
#pragma unroll
                for (int g = 0; g < 4; g++) {
                    float2 b = *(const float2*)&Bs[g][kk][cp * 2];
                    acc[g][0][0] += a.x * b.x;
                    acc[g][0][1] += a.y * b.x;
                    acc[g][0][2] += a.z * b.x;
                    acc[g][0][3] += a.w * b.x;
                    acc[g][1][0] += a.x * b.y;
                    acc[g][1][1] += a.y * b.y;
                    acc[g][1][2] += a.z * b.y;
                    acc[g][1][3] += a.w * b.y;
                }
            }
            __syncthreads();
        }

#pragma unroll
        for (int g = 0; g < 4; g++)
#pragma unroll
            for (int i = 0; i < 4; i++) {
                int row = r0 + i;
                float2 val = make_float2(acc[g][0][i], acc[g][1][i]);
                *(float2*)(g_part + (((size_t)ksb * BATCH + row) * 4 + g) * HDIM
                           + hc0 + cp * 2) = val;
            }

        grid_barrier(++bar_epoch * NBLOCKS);

        {
            const float* xp = g_xproj + ((size_t)t * BATCH + p2b) * 4 * HDIM;
            float2 v[4];
#pragma unroll
            for (int g = 0; g < 4; g++)
                v[g] = *(const float2*)(xp + (size_t)g * HDIM + p2hc);
#pragma unroll
            for (int ks = 0; ks < KSPLIT; ks++)
#pragma unroll
                for (int g = 0; g < 4; g++) {
                    float2 pv = *(const float2*)(g_part +
                        (((size_t)ks * BATCH + p2b) * 4 + g) * HDIM + p2hc);
                    v[g].x += pv.x;
                    v[g].y += pv.y;
                }

            float2 cold = *(const float2*)(g_c + idx2);
            float2 hnew, cnew;
            {
                float i_t = 1.0f / (1.0f + expf(-v[0].x));
                float f_t = 1.0f / (1.0f + expf(-v[1].x));
                float gg  = tanhf(v[2].x);
                float o_t = 1.0f / (1.0f + expf(-v[3].x));
                cnew.x = f_t * cold.x + i_t * gg;
                hnew.x = o_t * tanhf(cnew.x);
            }
            {
                float i_t = 1.0f / (1.0f + expf(-v[0].y));
                float f_t = 1.0f / (1.0f + expf(-v[1].y));
                float gg  = tanhf(v[2].y);
                float o_t = 1.0f / (1.0f + expf(-v[3].y));
                cnew.y = f_t * cold.y + i_t * gg;
                hnew.y = o_t * tanhf(cnew.y);
            }

            *(float2*)(g_c + idx2) = cnew;
            if (t == TSTEPS - 1) {
                *(float2*)(out + idx2) = hnew;
                *(float2*)(out + BATCH * HDIM + idx2) = cnew;
            } else {
                *(float2*)(&g_h[(t + 1) & 1][idx2]) = hnew;
            }
        }

        if (t != TSTEPS - 1)
            grid_barrier(++bar_epoch * NBLOCKS);
    }
}

// ---------------- launch ----------------
extern "C" void kernel_launch(void* const* d_in, const int* in_sizes, int n_in,
                              void* d_out, int out_size)
{
    const float* x    = (const float*)d_in[0];
    const float* Wii  = (const float*)d_in[1];
    const float* Whi  = (const float*)d_in[2];
    const float* b_hi = (const float*)d_in[3];
    const float* Wif  = (const float*)d_in[4];
    const float* Whf  = (const float*)d_in[5];
    const float* b_hf = (const float*)d_in[6];
    const float* Wig  = (const float*)d_in[7];
    const float* Whg  = (const float*)d_in[8];
    const float* b_hg = (const float*)d_in[9];
    const float* Wio  = (const float*)d_in[10];
    const float* Who  = (const float*)d_in[11];
    const float* b_ho = (const float*)d_in[12];
    float* out = (float*)d_out;

    cudaFuncSetAttribute(xproj_tc, cudaFuncAttributeMaxDynamicSharedMemorySize,
                         XP_SMEM_TOTAL);

    init_state<<<(BATCH * HDIM + 255) / 256, 256>>>();

    // bf16 splits
    split_x<<<(int)(((size_t)BATCH * TSTEPS * IDIM / 2) / 256), 256>>>(x);
    split_w<<<(int)(((size_t)IDIM * 4 * HDIM / 2) / 256), 256>>>(Wii, Wif, Wig, Wio);
    concat_bias<<<(4 * HDIM + 255) / 256, 256>>>(b_hi, b_hf, b_hg, b_ho);

    // tensor-core x projection: grid (m-blocks fast, n-blocks slow)
    dim3 gx(BATCH * TSTEPS / 128, 4 * HDIM / 256);
    xproj_tc<<<gx, 256, XP_SMEM_TOTAL>>>();

    lstm_persistent<<<NBLOCKS, 256>>>(Whi, Whf, Whg, Who, out);
}

// round 6
// speedup vs baseline: 2.3196x; 1.8774x over previous
#include <cuda_runtime.h>
#include <cuda_bf16.h>
#include <math.h>
#include <stdint.h>

#define BATCH 64
#define TSTEPS 512
#define IDIM 1024
#define HDIM 1024
#define KSPLIT 4
#define KC (HDIM / KSPLIT)   // 256
#define NBLOCKS 128

// ---------------- scratch (static device allocations only) ----------------
__device__ float g_xproj[(size_t)TSTEPS * BATCH * 4 * HDIM]; // [T][B][4H]
__device__ float g_c[BATCH * HDIM];
__device__ float g_part[(size_t)KSPLIT * BATCH * 4 * HDIM];  // [ks][b][n4096]
__device__ unsigned g_bar;

// bf16 split operands
__device__ __nv_bfloat16 g_xhi[(size_t)BATCH * TSTEPS * IDIM];
__device__ __nv_bfloat16 g_xlo[(size_t)BATCH * TSTEPS * IDIM];
__device__ __nv_bfloat16 g_wxhi[(size_t)IDIM * 4 * HDIM];    // [K][4096]
__device__ __nv_bfloat16 g_wxlo[(size_t)IDIM * 4 * HDIM];
__device__ __nv_bfloat16 g_whhi[(size_t)HDIM * 4 * HDIM];    // [K][4096]
__device__ __nv_bfloat16 g_whlo[(size_t)HDIM * 4 * HDIM];
__device__ float g_bx[4 * HDIM];

// h state as bf16 hi/lo ping-pong
__device__ __nv_bfloat16 g_hhi[2][BATCH * HDIM];
__device__ __nv_bfloat16 g_hlo[2][BATCH * HDIM];

// ---------------- init ----------------
__global__ void init_state() {
    int i = blockIdx.x * blockDim.x + threadIdx.x;
    if (i == 0) g_bar = 0;
    if (i < BATCH * HDIM) {
        g_hhi[0][i] = __float2bfloat16(0.0f);
        g_hlo[0][i] = __float2bfloat16(0.0f);
        g_c[i] = 0.0f;
    }
}

// ---------------- bf16 hi/lo split kernels ----------------
__global__ __launch_bounds__(256) void split_x(const float* __restrict__ x) {
    size_t i = (size_t)blockIdx.x * blockDim.x + threadIdx.x;
    float2 v = ((const float2*)x)[i];
    __nv_bfloat16 h0 = __float2bfloat16(v.x);
    __nv_bfloat16 h1 = __float2bfloat16(v.y);
    __nv_bfloat16 l0 = __float2bfloat16(v.x - __bfloat162float(h0));
    __nv_bfloat16 l1 = __float2bfloat16(v.y - __bfloat162float(h1));
    __nv_bfloat162 hp; hp.x = h0; hp.y = h1;
    __nv_bfloat162 lp; lp.x = l0; lp.y = l1;
    ((__nv_bfloat162*)g_xhi)[i] = hp;
    ((__nv_bfloat162*)g_xlo)[i] = lp;
}

// which == 0 -> write g_wxhi/g_wxlo, which == 1 -> g_whhi/g_whlo.
// Destination pointers resolved IN DEVICE CODE (passing __device__ globals as
// kernel args from host passes the host shadow address — silent ATS write).
__global__ __launch_bounds__(256) void split_w4(
    const float* __restrict__ W0, const float* __restrict__ W1,
    const float* __restrict__ W2, const float* __restrict__ W3,
    int which)
{
    __nv_bfloat16* hi = which ? g_whhi : g_wxhi;
    __nv_bfloat16* lo = which ? g_whlo : g_wxlo;
    size_t i = (size_t)blockIdx.x * blockDim.x + threadIdx.x;   // per 2 elems
    size_t n2 = i * 2;
    int k = (int)(n2 >> 12);
    int n = (int)(n2 & 4095);
    int gate = n >> 10;
    int col = n & 1023;
    const float* W = (gate == 0) ? W0 : (gate == 1) ? W1 : (gate == 2) ? W2 : W3;
    float2 v = *(const float2*)(W + (size_t)k * HDIM + col);
    __nv_bfloat16 h0 = __float2bfloat16(v.x);
    __nv_bfloat16 h1 = __float2bfloat16(v.y);
    __nv_bfloat16 l0 = __float2bfloat16(v.x - __bfloat162float(h0));
    __nv_bfloat16 l1 = __float2bfloat16(v.y - __bfloat162float(h1));
    __nv_bfloat162 hp; hp.x = h0; hp.y = h1;
    __nv_bfloat162 lp; lp.x = l0; lp.y = l1;
    ((__nv_bfloat162*)hi)[i] = hp;
    ((__nv_bfloat162*)lo)[i] = lp;
}

__global__ void concat_bias(
    const float* __restrict__ b0, const float* __restrict__ b1,
    const float* __restrict__ b2, const float* __restrict__ b3)
{
    int i = blockIdx.x * blockDim.x + threadIdx.x;
    if (i < 4 * HDIM) {
        int gate = i >> 10;
        const float* b = (gate == 0) ? b0 : (gate == 1) ? b1 : (gate == 2) ? b2 : b3;
        g_bx[i] = b[i & 1023];
    }
}

// ---------------- common PTX macros ----------------
#define CP_ASYNC16(dst_u32, src_ptr) \
    asm volatile("cp.async.cg.shared.global [%0], [%1], 16;" :: "r"(dst_u32), "l"(src_ptr))
#define CP_COMMIT() asm volatile("cp.async.commit_group;")

#define LDSM4(R, addr) \
    asm volatile("ldmatrix.sync.aligned.m8n8.x4.shared.b16 {%0,%1,%2,%3}, [%4];" \
        : "=r"((R)[0]), "=r"((R)[1]), "=r"((R)[2]), "=r"((R)[3]) : "r"(addr))
#define LDSM4T(R, addr) \
    asm volatile("ldmatrix.sync.aligned.m8n8.x4.trans.shared.b16 {%0,%1,%2,%3}, [%4];" \
        : "=r"((R)[0]), "=r"((R)[1]), "=r"((R)[2]), "=r"((R)[3]) : "r"(addr))

#define MMA_BF16(C, A, B0, B1) \
    asm volatile("mma.sync.aligned.m16n8k16.row.col.f32.bf16.bf16.f32 " \
        "{%0,%1,%2,%3}, {%4,%5,%6,%7}, {%8,%9}, {%0,%1,%2,%3};" \
        : "+f"((C)[0]), "+f"((C)[1]), "+f"((C)[2]), "+f"((C)[3]) \
        : "r"((A)[0]), "r"((A)[1]), "r"((A)[2]), "r"((A)[3]), "r"(B0), "r"(B1))

// ---------------- tensor-core x-projection (unchanged, known-good) --------
#define XP_SAS_B 80
#define XP_SBS_B 528
#define XP_A_BUF 10240
#define XP_B_BUF 16896
#define XP_A_OFF(st, hl) ((st) * 20480 + (hl) * XP_A_BUF)
#define XP_B_OFF(st, hl) (40960 + (st) * 33792 + (hl) * XP_B_BUF)
#define XP_SMEM_TOTAL 108544

__global__ __launch_bounds__(256) void xproj_tc()
{
    extern __shared__ __align__(16) char xsm[];
    uint32_t smemu = (uint32_t)__cvta_generic_to_shared(xsm);

    const int tid  = threadIdx.x;
    const int wid  = tid >> 5;
    const int lane = tid & 31;
    const int wm64 = (wid & 1) * 64;
    const int wn64 = (wid >> 1) * 64;
    const int m0 = blockIdx.x * 128;
    const int n0 = blockIdx.y * 256;

    float acc[4][8][4];
#pragma unroll
    for (int mt = 0; mt < 4; mt++)
#pragma unroll
        for (int nt = 0; nt < 8; nt++)
#pragma unroll
            for (int q = 0; q < 4; q++) acc[mt][nt][q] = 0.0f;

    const int NKB = IDIM / 32;

    auto issue = [&](int kb) {
        int st = kb & 1;
        int k0 = kb * 32;
#pragma unroll
        for (int j = 0; j < 4; j++) {
            int idx = tid + j * 256;
            int hl  = idx >> 9;
            int rem = idx & 511;
            int row = rem >> 2;
            int c   = rem & 3;
            const __nv_bfloat16* src = (hl ? g_xlo : g_xhi)
                + (size_t)(m0 + row) * IDIM + k0 + c * 8;
            uint32_t dst = smemu + XP_A_OFF(st, hl) + row * XP_SAS_B + c * 16;
            CP_ASYNC16(dst, src);
        }
#pragma unroll
        for (int j = 0; j < 8; j++) {
            int idx = tid + j * 256;
            int hl  = idx >> 10;
            int rem = idx & 1023;
            int row = rem >> 5;
            int c   = rem & 31;
            const __nv_bfloat16* src = (hl ? g_wxlo : g_wxhi)
                + (size_t)(k0 + row) * 4096 + n0 + c * 8;
            uint32_t dst = smemu + XP_B_OFF(st, hl) + row * XP_SBS_B + c * 16;
            CP_ASYNC16(dst, src);
        }
        CP_COMMIT();
    };

    issue(0);

    const int lrow  = lane & 15;
    const int lhalf = lane >> 4;
    const int brow  = (lane & 7) + ((lane >> 3) & 1) * 8;
    const int bcolo = (lane >> 4) * 8;

    for (int kb = 0; kb < NKB; kb++) {
        if (kb + 1 < NKB) issue(kb + 1);
        if (kb + 1 < NKB) asm volatile("cp.async.wait_group 1;");
        else              asm volatile("cp.async.wait_group 0;");
        __syncthreads();

        int st = kb & 1;
#pragma unroll
        for (int kstep = 0; kstep < 2; kstep++) {
            uint32_t ah[4][4], al[4][4], bh[4][4], bl[4][4];
#pragma unroll
            for (int mt = 0; mt < 4; mt++) {
                uint32_t base = smemu + (wm64 + mt * 16 + lrow) * XP_SAS_B
                              + lhalf * 16 + kstep * 32;
                LDSM4(ah[mt], base + XP_A_OFF(st, 0));
                LDSM4(al[mt], base + XP_A_OFF(st, 1));
            }
#pragma unroll
            for (int nt2 = 0; nt2 < 4; nt2++) {
                uint32_t base = smemu + (kstep * 16 + brow) * XP_SBS_B
                              + (wn64 + nt2 * 16 + bcolo) * 2;
                LDSM4T(bh[nt2], base + XP_B_OFF(st, 0));
                LDSM4T(bl[nt2], base + XP_B_OFF(st, 1));
            }
#pragma unroll
            for (int mt = 0; mt < 4; mt++)
#pragma unroll
                for (int nt = 0; nt < 8; nt++) {
                    int p = nt >> 1, q = (nt & 1) * 2;
                    MMA_BF16(acc[mt][nt], ah[mt], bh[p][q], bh[p][q + 1]);
                    MMA_BF16(acc[mt][nt], ah[mt], bl[p][q], bl[p][q + 1]);
                    MMA_BF16(acc[mt][nt], al[mt], bh[p][q], bh[p][q + 1]);
                }
        }
        __syncthreads();
    }

    const int g  = lane >> 2;
    const int tg = lane & 3;
#pragma unroll
    for (int mt = 0; mt < 4; mt++) {
        int row0 = m0 + wm64 + mt * 16 + g;
        int row1 = row0 + 8;
        int b0 = row0 >> 9, t0 = row0 & 511;
        int b1 = row1 >> 9, t1 = row1 & 511;
        float* dst0 = g_xproj + ((size_t)(t0 * BATCH + b0) << 12);
        float* dst1 = g_xproj + ((size_t)(t1 * BATCH + b1) << 12);
#pragma unroll
        for (int nt = 0; nt < 8; nt++) {
            int nglob = n0 + wn64 + nt * 8 + tg * 2;
            float2 bias = *(const float2*)(g_bx + nglob);
            float2 o0 = make_float2(acc[mt][nt][0] + bias.x, acc[mt][nt][1] + bias.y);
            float2 o1 = make_float2(acc[mt][nt][2] + bias.x, acc[mt][nt][3] + bias.y);
            *(float2*)(dst0 + nglob) = o0;
            *(float2*)(dst1 + nglob) = o1;
        }
    }
}

// ---------------- grid barrier ----------------
__device__ __forceinline__ void grid_barrier(unsigned target) {
    __syncthreads();
    if (threadIdx.x == 0) {
        __threadfence();
        atomicAdd(&g_bar, 1u);
        volatile unsigned* p = &g_bar;
        while (*p < target) { __nanosleep(64); }
        __threadfence();
    }
    __syncthreads();
}

// ---------------- persistent tensor-core recurrence ----------------
// 128 blocks = 32 n-tiles (128 cols of 4096) x 4 k-splits (256 of 1024).
// Wh hi/lo slice resident in smem. Per step:
//   phase1: partial = h(hi/lo) @ Wh slice via 3-pass mma.sync
//   barrier; phase2: reduce + gates + write h hi/lo split; barrier.
#define WH_STRIDE 272                    // 128 halves * 2B + 16 pad
#define WH_HALF_BYTES (KC * WH_STRIDE)   // 69632
#define RC_SAS 80                        // A row stride bytes
#define RC_A_OFF(st, hl) (2 * WH_HALF_BYTES + (st) * 10240 + (hl) * 5120)
#define RC_SMEM_TOTAL (2 * WH_HALF_BYTES + 20480)   // 159744

__global__ __launch_bounds__(256, 1) void lstm_persistent_tc(float* __restrict__ out)
{
    extern __shared__ __align__(16) char rsm[];
    uint32_t smemu = (uint32_t)__cvta_generic_to_shared(rsm);

    const int tid  = threadIdx.x;
    const int wid  = tid >> 5;
    const int lane = tid & 31;
    const int ksb  = blockIdx.x >> 5;          // k-split 0..3
    const int nblk0 = (blockIdx.x & 31) * 128; // n-tile base in [0,4096)
    const int kbase0 = ksb * KC;

    // ---- preload Wh slice (hi+lo) into smem ----
    for (int h = 0; h < 2; h++) {
        const __nv_bfloat16* W = h ? g_whlo : g_whhi;
        for (int i = tid; i < KC * 16; i += 256) {
            int kl = i >> 4;
            int c  = i & 15;
            const __nv_bfloat16* src = W + (size_t)(kbase0 + kl) * 4096 + nblk0 + c * 8;
            float4 v = *(const float4*)src;
            *(float4*)(rsm + h * WH_HALF_BYTES + kl * WH_STRIDE + c * 16) = v;
        }
    }
    __syncthreads();

    const int wm0 = (wid & 1) * 32;
    const int wn0 = (wid >> 1) * 32;
    const int lrow  = lane & 15;
    const int lhalf = lane >> 4;
    const int brow  = (lane & 7) + ((lane >> 3) & 1) * 8;
    const int bcolo = (lane >> 4) * 8;

    const int idx2 = ((int)blockIdx.x * 256 + tid) * 2;   // 0..65534
    const int p2b  = idx2 >> 10;
    const int p2hc = idx2 & (HDIM - 1);

    unsigned bar_epoch = 0;

    for (int t = 0; t < TSTEPS; t++) {
        const __nv_bfloat16* hhi = g_hhi[t & 1];
        const __nv_bfloat16* hlo = g_hlo[t & 1];

        float acc[2][4][4];
#pragma unroll
        for (int mt = 0; mt < 2; mt++)
#pragma unroll
            for (int nt = 0; nt < 4; nt++)
#pragma unroll
                for (int q = 0; q < 4; q++) acc[mt][nt][q] = 0.0f;

        auto issueA = [&](int kb) {
            int st = kb & 1;
            int kglob = kbase0 + kb * 32;
#pragma unroll
            for (int j = 0; j < 2; j++) {
                int idx = tid + j * 256;       // 0..511
                int hl  = idx >> 8;
                int rem = idx & 255;
                int row = rem >> 2;            // 0..63
                int c   = rem & 3;
                const __nv_bfloat16* src = (hl ? hlo : hhi)
                    + (size_t)row * HDIM + kglob + c * 8;
                uint32_t dst = smemu + RC_A_OFF(st, hl) + row * RC_SAS + c * 16;
                CP_ASYNC16(dst, src);
            }
            CP_COMMIT();
        };

        issueA(0);
#pragma unroll
        for (int kb = 0; kb < 8; kb++) {
            if (kb + 1 < 8) issueA(kb + 1);
            if (kb + 1 < 8) asm volatile("cp.async.wait_group 1;");
            else            asm volatile("cp.async.wait_group 0;");
            __syncthreads();

            int st = kb & 1;
#pragma unroll
            for (int kstep = 0; kstep < 2; kstep++) {
                uint32_t ah[2][4], al[2][4], bh[2][4], bl[2][4];
#pragma unroll
                for (int mt = 0; mt < 2; mt++) {
                    uint32_t base = smemu + (wm0 + mt * 16 + lrow) * RC_SAS
                                  + lhalf * 16 + kstep * 32;
                    LDSM4(ah[mt], base + RC_A_OFF(st, 0));
                    LDSM4(al[mt], base + RC_A_OFF(st, 1));
                }
                int klocal = kb * 32 + kstep * 16 + brow;
#pragma unroll
                for (int p = 0; p < 2; p++) {
                    uint32_t base = smemu + klocal * WH_STRIDE
                                  + (wn0 + p * 16 + bcolo) * 2;
                    LDSM4T(bh[p], base);
                    LDSM4T(bl[p], base + WH_HALF_BYTES);
                }
#pragma unroll
                for (int mt = 0; mt < 2; mt++)
#pragma unroll
                    for (int nt = 0; nt < 4; nt++) {
                        int p = nt >> 1, q = (nt & 1) * 2;
                        MMA_BF16(acc[mt][nt], ah[mt], bh[p][q], bh[p][q + 1]);
                        MMA_BF16(acc[mt][nt], ah[mt], bl[p][q], bl[p][q + 1]);
                        MMA_BF16(acc[mt][nt], al[mt], bh[p][q], bh[p][q + 1]);
                    }
            }
            __syncthreads();
        }

#pragma unroll
        for (int mt = 0; mt < 2; mt++) {
            int r0 = wm0 + mt * 16 + (lane >> 2);
            int r1 = r0 + 8;
#pragma unroll
            for (int nt = 0; nt < 4; nt++) {
                int n = nblk0 + wn0 + nt * 8 + (lane & 3) * 2;
                *(float2*)(g_part + ((size_t)(ksb * BATCH + r0) << 12) + n) =
                    make_float2(acc[mt][nt][0], acc[mt][nt][1]);
                *(float2*)(g_part + ((size_t)(ksb * BATCH + r1) << 12) + n) =
                    make_float2(acc[mt][nt][2], acc[mt][nt][3]);
            }
        }

        grid_barrier(++bar_epoch * NBLOCKS);

        {
            const float* xp = g_xproj + ((size_t)(t * BATCH + p2b) << 12);
            float2 v[4];
#pragma unroll
            for (int g = 0; g < 4; g++) {
                v[g] = *(const float2*)(xp + (g << 10) + p2hc);
#pragma unroll
                for (int ks = 0; ks < KSPLIT; ks++) {
                    float2 pv = *(const float2*)(g_part +
                        ((size_t)(ks * BATCH + p2b) << 12) + (g << 10) + p2hc);
                    v[g].x += pv.x;
                    v[g].y += pv.y;
                }
            }

            float2 cold = *(const float2*)(g_c + idx2);
            float2 hnew, cnew;
            {
                float i_t = 1.0f / (1.0f + expf(-v[0].x));
                float f_t = 1.0f / (1.0f + expf(-v[1].x));
                float gg  = tanhf(v[2].x);
                float o_t = 1.0f / (1.0f + expf(-v[3].x));
                cnew.x = f_t * cold.x + i_t * gg;
                hnew.x = o_t * tanhf(cnew.x);
            }
            {
                float i_t = 1.0f / (1.0f + expf(-v[0].y));
                float f_t = 1.0f / (1.0f + expf(-v[1].y));
                float gg  = tanhf(v[2].y);
                float o_t = 1.0f / (1.0f + expf(-v[3].y));
                cnew.y = f_t * cold.y + i_t * gg;
                hnew.y = o_t * tanhf(cnew.y);
            }

            *(float2*)(g_c + idx2) = cnew;
            if (t == TSTEPS - 1) {
                *(float2*)(out + idx2) = hnew;
                *(float2*)(out + BATCH * HDIM + idx2) = cnew;
            } else {
                __nv_bfloat16 h0 = __float2bfloat16(hnew.x);
                __nv_bfloat16 h1 = __float2bfloat16(hnew.y);
                __nv_bfloat16 l0 = __float2bfloat16(hnew.x - __bfloat162float(h0));
                __nv_bfloat16 l1 = __float2bfloat16(hnew.y - __bfloat162float(h1));
                __nv_bfloat162 hp; hp.x = h0; hp.y = h1;
                __nv_bfloat162 lp; lp.x = l0; lp.y = l1;
                *(__nv_bfloat162*)(&g_hhi[(t + 1) & 1][idx2]) = hp;
                *(__nv_bfloat162*)(&g_hlo[(t + 1) & 1][idx2]) = lp;
            }
        }

        if (t != TSTEPS - 1)
            grid_barrier(++bar_epoch * NBLOCKS);
    }
}

// ---------------- launch ----------------
extern "C" void kernel_launch(void* const* d_in, const int* in_sizes, int n_in,
                              void* d_out, int out_size)
{
    const float* x    = (const float*)d_in[0];
    const float* Wii  = (const float*)d_in[1];
    const float* Whi  = (const float*)d_in[2];
    const float* b_hi = (const float*)d_in[3];
    const float* Wif  = (const float*)d_in[4];
    const float* Whf  = (const float*)d_in[5];
    const float* b_hf = (const float*)d_in[6];
    const float* Wig  = (const float*)d_in[7];
    const float* Whg  = (const float*)d_in[8];
    const float* b_hg = (const float*)d_in[9];
    const float* Wio  = (const float*)d_in[10];
    const float* Who  = (const float*)d_in[11];
    const float* b_ho = (const float*)d_in[12];
    float* out = (float*)d_out;

    cudaFuncSetAttribute(xproj_tc, cudaFuncAttributeMaxDynamicSharedMemorySize,
                         XP_SMEM_TOTAL);
    cudaFuncSetAttribute(lstm_persistent_tc, cudaFuncAttributeMaxDynamicSharedMemorySize,
                         RC_SMEM_TOTAL);

    init_state<<<(BATCH * HDIM + 255) / 256, 256>>>();

    split_x<<<(int)(((size_t)BATCH * TSTEPS * IDIM / 2) / 256), 256>>>(x);
    split_w4<<<(int)(((size_t)IDIM * 4 * HDIM / 2) / 256), 256>>>(
        Wii, Wif, Wig, Wio, 0);
    split_w4<<<(int)(((size_t)HDIM * 4 * HDIM / 2) / 256), 256>>>(
        Whi, Whf, Whg, Who, 1);
    concat_bias<<<(4 * HDIM + 255) / 256, 256>>>(b_hi, b_hf, b_hg, b_ho);

    dim3 gx(BATCH * TSTEPS / 128, 4 * HDIM / 256);
    xproj_tc<<<gx, 256, XP_SMEM_TOTAL>>>();

    lstm_persistent_tc<<<NBLOCKS, 256, RC_SMEM_TOTAL>>>(out);
}

// round 8
// speedup vs baseline: 2.4129x; 1.0402x over previous
#include <cuda_runtime.h>
#include <cuda_bf16.h>
#include <math.h>
#include <stdint.h>

#define BATCH 64
#define TSTEPS 512
#define IDIM 1024
#define HDIM 1024
#define KSPLIT 4
#define KC (HDIM / KSPLIT)   // 256
#define NBLOCKS 128

// ---------------- scratch (static device allocations only) ----------------
__device__ float g_xproj[(size_t)TSTEPS * BATCH * 4 * HDIM]; // [T][B][4H]
__device__ float g_c[BATCH * HDIM];
__device__ float g_part[(size_t)KSPLIT * BATCH * 4 * HDIM];  // [ks][b][n4096]
__device__ unsigned g_bar;

// bf16 split operands ([K][4096] layout for both weight sets)
__device__ __nv_bfloat16 g_xhi[(size_t)BATCH * TSTEPS * IDIM];   // [M][K]
__device__ __nv_bfloat16 g_xlo[(size_t)BATCH * TSTEPS * IDIM];
__device__ __nv_bfloat16 g_wxhi[(size_t)IDIM * 4 * HDIM];
__device__ __nv_bfloat16 g_wxlo[(size_t)IDIM * 4 * HDIM];
__device__ __nv_bfloat16 g_whhi[(size_t)HDIM * 4 * HDIM];
__device__ __nv_bfloat16 g_whlo[(size_t)HDIM * 4 * HDIM];
__device__ float g_bx[4 * HDIM];

// h state as bf16 hi/lo ping-pong
__device__ __nv_bfloat16 g_hhi[2][BATCH * HDIM];
__device__ __nv_bfloat16 g_hlo[2][BATCH * HDIM];

// ---------------- init ----------------
__global__ void init_state() {
    int i = blockIdx.x * blockDim.x + threadIdx.x;
    if (i == 0) g_bar = 0;
    if (i < BATCH * HDIM) {
        g_hhi[0][i] = __float2bfloat16(0.0f);
        g_hlo[0][i] = __float2bfloat16(0.0f);
        g_c[i] = 0.0f;
    }
}

// ---------------- bf16 hi/lo split kernels ----------------
__global__ __launch_bounds__(256) void split_x(const float* __restrict__ x) {
    size_t i = (size_t)blockIdx.x * blockDim.x + threadIdx.x;
    float2 v = ((const float2*)x)[i];
    __nv_bfloat16 h0 = __float2bfloat16(v.x);
    __nv_bfloat16 h1 = __float2bfloat16(v.y);
    __nv_bfloat16 l0 = __float2bfloat16(v.x - __bfloat162float(h0));
    __nv_bfloat16 l1 = __float2bfloat16(v.y - __bfloat162float(h1));
    __nv_bfloat162 hp; hp.x = h0; hp.y = h1;
    __nv_bfloat162 lp; lp.x = l0; lp.y = l1;
    ((__nv_bfloat162*)g_xhi)[i] = hp;
    ((__nv_bfloat162*)g_xlo)[i] = lp;
}

// which == 0 -> g_wxhi/g_wxlo, which == 1 -> g_whhi/g_whlo.
// Destination pointers resolved IN DEVICE CODE.
__global__ __launch_bounds__(256) void split_w4(
    const float* __restrict__ W0, const float* __restrict__ W1,
    const float* __restrict__ W2, const float* __restrict__ W3,
    int which)
{
    __nv_bfloat16* hi = which ? g_whhi : g_wxhi;
    __nv_bfloat16* lo = which ? g_whlo : g_wxlo;
    size_t i = (size_t)blockIdx.x * blockDim.x + threadIdx.x;   // per 2 elems
    size_t n2 = i * 2;
    int k = (int)(n2 >> 12);
    int n = (int)(n2 & 4095);
    int gate = n >> 10;
    int col = n & 1023;
    const float* W = (gate == 0) ? W0 : (gate == 1) ? W1 : (gate == 2) ? W2 : W3;
    float2 v = *(const float2*)(W + (size_t)k * HDIM + col);
    __nv_bfloat16 h0 = __float2bfloat16(v.x);
    __nv_bfloat16 h1 = __float2bfloat16(v.y);
    __nv_bfloat16 l0 = __float2bfloat16(v.x - __bfloat162float(h0));
    __nv_bfloat16 l1 = __float2bfloat16(v.y - __bfloat162float(h1));
    __nv_bfloat162 hp; hp.x = h0; hp.y = h1;
    __nv_bfloat162 lp; lp.x = l0; lp.y = l1;
    ((__nv_bfloat162*)hi)[i] = hp;
    ((__nv_bfloat162*)lo)[i] = lp;
}

__global__ void concat_bias(
    const float* __restrict__ b0, const float* __restrict__ b1,
    const float* __restrict__ b2, const float* __restrict__ b3)
{
    int i = blockIdx.x * blockDim.x + threadIdx.x;
    if (i < 4 * HDIM) {
        int gate = i >> 10;
        const float* b = (gate == 0) ? b0 : (gate == 1) ? b1 : (gate == 2) ? b2 : b3;
        g_bx[i] = b[i & 1023];
    }
}

// ---------------- common PTX macros ----------------
#define CP_ASYNC16(dst_u32, src_ptr) \
    asm volatile("cp.async.cg.shared.global [%0], [%1], 16;" :: "r"(dst_u32), "l"(src_ptr))
#define CP_COMMIT() asm volatile("cp.async.commit_group;")

#define LDSM4(R, addr) \
    asm volatile("ldmatrix.sync.aligned.m8n8.x4.shared.b16 {%0,%1,%2,%3}, [%4];" \
        : "=r"((R)[0]), "=r"((R)[1]), "=r"((R)[2]), "=r"((R)[3]) : "r"(addr))
#define LDSM4T(R, addr) \
    asm volatile("ldmatrix.sync.aligned.m8n8.x4.trans.shared.b16 {%0,%1,%2,%3}, [%4];" \
        : "=r"((R)[0]), "=r"((R)[1]), "=r"((R)[2]), "=r"((R)[3]) : "r"(addr))

#define MMA_BF16(C, A, B0, B1) \
    asm volatile("mma.sync.aligned.m16n8k16.row.col.f32.bf16.bf16.f32 " \
        "{%0,%1,%2,%3}, {%4,%5,%6,%7}, {%8,%9}, {%0,%1,%2,%3};" \
        : "+f"((C)[0]), "+f"((C)[1]), "+f"((C)[2]), "+f"((C)[3]) \
        : "r"((A)[0]), "r"((A)[1]), "r"((A)[2]), "r"((A)[3]), "r"(B0), "r"(B1))

// ---------------- tensor-core x-projection, v2 ----------------
// Block 128m x 256n, 512 threads (16 warps, 4x4), warp tile 32m x 64n.
// 3-stage cp.async pipeline, BK=32, single __syncthreads per chunk.
// 3-pass bf16 split: hi*hi + hi*lo + lo*hi.
#define XQ_SAS 80                         // A smem row stride (32 halves + pad)
#define XQ_SBS 528                        // B smem row stride (256 halves + pad)
#define XQ_A_BUF 10240                    // 128 * 80
#define XQ_B_BUF 16896                    // 32 * 528
#define XQ_STAGE (2 * XQ_A_BUF + 2 * XQ_B_BUF)       // 54272
#define XQ_A_OFF(st, hl) ((st) * XQ_STAGE + (hl) * XQ_A_BUF)
#define XQ_B_OFF(st, hl) ((st) * XQ_STAGE + 2 * XQ_A_BUF + (hl) * XQ_B_BUF)
#define XQ_SMEM (3 * XQ_STAGE)            // 162816

__global__ __launch_bounds__(512, 1) void xproj_tc2()
{
    extern __shared__ __align__(16) char xsm[];
    uint32_t smemu = (uint32_t)__cvta_generic_to_shared(xsm);

    const int tid  = threadIdx.x;
    const int wid  = tid >> 5;
    const int lane = tid & 31;
    const int wm = (wid & 3) * 32;       // warp m offset
    const int wn = (wid >> 2) * 64;      // warp n offset
    const int m0 = blockIdx.x * 128;     // m fastest (B n-slice L2-resident)
    const int n0 = blockIdx.y * 256;

    float acc[2][8][4];
#pragma unroll
    for (int mt = 0; mt < 2; mt++)
#pragma unroll
        for (int nt = 0; nt < 8; nt++)
#pragma unroll
            for (int q = 0; q < 4; q++) acc[mt][nt][q] = 0.0f;

    auto issue = [&](int kb) {
        int st = kb % 3;
        int k0 = kb * 32;
        // A hi/lo: 128 rows x 32 halves; 1024 16B-chunks, 2 per thread
#pragma unroll
        for (int j = 0; j < 2; j++) {
            int idx = tid + j * 512;
            int hl  = idx >> 9;
            int rem = idx & 511;
            int row = rem >> 2;
            int c   = rem & 3;
            const __nv_bfloat16* src = (hl ? g_xlo : g_xhi)
                + (size_t)(m0 + row) * IDIM + k0 + c * 8;
            uint32_t dst = smemu + XQ_A_OFF(st, hl) + row * XQ_SAS + c * 16;
            CP_ASYNC16(dst, src);
        }
        // B hi/lo: 32 rows x 256 halves; 2048 16B-chunks, 4 per thread
#pragma unroll
        for (int j = 0; j < 4; j++) {
            int idx = tid + j * 512;
            int hl  = idx >> 10;
            int rem = idx & 1023;
            int row = rem >> 5;
            int c   = rem & 31;
            const __nv_bfloat16* src = (hl ? g_wxlo : g_wxhi)
                + (size_t)(k0 + row) * 4096 + n0 + c * 8;
            uint32_t dst = smemu + XQ_B_OFF(st, hl) + row * XQ_SBS + c * 16;
            CP_ASYNC16(dst, src);
        }
        CP_COMMIT();
    };

    issue(0);
    issue(1);

    const int lrow  = lane & 15;
    const int lhalf = lane >> 4;
    const int brow  = (lane & 7) + ((lane >> 3) & 1) * 8;
    const int bcolo = (lane >> 4) * 8;

    for (int kb = 0; kb < 32; kb++) {
        int st = kb % 3;
        asm volatile("cp.async.wait_group 1;");
        __syncthreads();

#pragma unroll
        for (int kstep = 0; kstep < 2; kstep++) {
            uint32_t ah[2][4], al[2][4];
#pragma unroll
            for (int mt = 0; mt < 2; mt++) {
                uint32_t base = smemu + (wm + mt * 16 + lrow) * XQ_SAS
                              + lhalf * 16 + kstep * 32;
                LDSM4(ah[mt], base + XQ_A_OFF(st, 0));
                LDSM4(al[mt], base + XQ_A_OFF(st, 1));
            }
            // B in two halves to cap register pressure
#pragma unroll
            for (int half = 0; half < 2; half++) {
                uint32_t bh[2][4], bl[2][4];
#pragma unroll
                for (int p = 0; p < 2; p++) {
                    int nt2 = half * 2 + p;
                    uint32_t base = smemu + (kstep * 16 + brow) * XQ_SBS
                                  + (wn + nt2 * 16 + bcolo) * 2;
                    LDSM4T(bh[p], base + XQ_B_OFF(st, 0));
                    LDSM4T(bl[p], base + XQ_B_OFF(st, 1));
                }
#pragma unroll
                for (int mt = 0; mt < 2; mt++)
#pragma unroll
                    for (int ntl = 0; ntl < 4; ntl++) {
                        int nt = half * 4 + ntl;
                        int p = ntl >> 1, q = (ntl & 1) * 2;
                        MMA_BF16(acc[mt][nt], ah[mt], bh[p][q], bh[p][q + 1]);
                        MMA_BF16(acc[mt][nt], ah[mt], bl[p][q], bl[p][q + 1]);
                        MMA_BF16(acc[mt][nt], al[mt], bh[p][q], bh[p][q + 1]);
                    }
            }
        }
        // issue into stage (kb+2)%3 == (kb-1)%3: its readers all finished
        // before this iteration's __syncthreads. Safe with 3 buffers.
        if (kb + 2 < 32) issue(kb + 2);
    }

    // ---- epilogue: bias + time-major scatter ----
    const int g  = lane >> 2;
    const int tg = lane & 3;
#pragma unroll
    for (int mt = 0; mt < 2; mt++) {
        int row0 = m0 + wm + mt * 16 + g;
        int row1 = row0 + 8;
        int b0 = row0 >> 9, t0 = row0 & 511;
        int b1 = row1 >> 9, t1 = row1 & 511;
        float* dst0 = g_xproj + ((size_t)(t0 * BATCH + b0) << 12);
        float* dst1 = g_xproj + ((size_t)(t1 * BATCH + b1) << 12);
#pragma unroll
        for (int nt = 0; nt < 8; nt++) {
            int nglob = n0 + wn + nt * 8 + tg * 2;
            float2 bias = *(const float2*)(g_bx + nglob);
            float2 o0 = make_float2(acc[mt][nt][0] + bias.x, acc[mt][nt][1] + bias.y);
            float2 o1 = make_float2(acc[mt][nt][2] + bias.x, acc[mt][nt][3] + bias.y);
            *(float2*)(dst0 + nglob) = o0;
            *(float2*)(dst1 + nglob) = o1;
        }
    }
}

// ---------------- grid barrier ----------------
__device__ __forceinline__ void grid_barrier(unsigned target) {
    __syncthreads();
    if (threadIdx.x == 0) {
        __threadfence();
        atomicAdd(&g_bar, 1u);
        volatile unsigned* p = &g_bar;
        while (*p < target) { __nanosleep(64); }
        __threadfence();
    }
    __syncthreads();
}

// ---------------- persistent tensor-core recurrence (R6, passing) --------
#define WH_STRIDE 272
#define WH_HALF_BYTES (KC * WH_STRIDE)   // 69632
#define RC_SAS 80
#define RC_A_OFF(st, hl) (2 * WH_HALF_BYTES + (st) * 10240 + (hl) * 5120)
#define RC_SMEM_TOTAL (2 * WH_HALF_BYTES + 20480)   // 159744

__global__ __launch_bounds__(256, 1) void lstm_persistent_tc(float* __restrict__ out)
{
    extern __shared__ __align__(16) char rsm[];
    uint32_t smemu = (uint32_t)__cvta_generic_to_shared(rsm);

    const int tid  = threadIdx.x;
    const int wid  = tid >> 5;
    const int lane = tid & 31;
    const int ksb  = blockIdx.x >> 5;
    const int nblk0 = (blockIdx.x & 31) * 128;
    const int kbase0 = ksb * KC;

    for (int h = 0; h < 2; h++) {
        const __nv_bfloat16* W = h ? g_whlo : g_whhi;
        for (int i = tid; i < KC * 16; i += 256) {
            int kl = i >> 4;
            int c  = i & 15;
            const __nv_bfloat16* src = W + (size_t)(kbase0 + kl) * 4096 + nblk0 + c * 8;
            float4 v = *(const float4*)src;
            *(float4*)(rsm + h * WH_HALF_BYTES + kl * WH_STRIDE + c * 16) = v;
        }
    }
    __syncthreads();

    const int wm0 = (wid & 1) * 32;
    const int wn0 = (wid >> 1) * 32;
    const int lrow  = lane & 15;
    const int lhalf = lane >> 4;
    const int brow  = (lane & 7) + ((lane >> 3) & 1) * 8;
    const int bcolo = (lane >> 4) * 8;

    const int idx2 = ((int)blockIdx.x * 256 + tid) * 2;
    const int p2b  = idx2 >> 10;
    const int p2hc = idx2 & (HDIM - 1);

    unsigned bar_epoch = 0;

    for (int t = 0; t < TSTEPS; t++) {
        const __nv_bfloat16* hhi = g_hhi[t & 1];
        const __nv_bfloat16* hlo = g_hlo[t & 1];

        float acc[2][4][4];
#pragma unroll
        for (int mt = 0; mt < 2; mt++)
#pragma unroll
            for (int nt = 0; nt < 4; nt++)
#pragma unroll
                for (int q = 0; q < 4; q++) acc[mt][nt][q] = 0.0f;

        auto issueA = [&](int kb) {
            int st = kb & 1;
            int kglob = kbase0 + kb * 32;
#pragma unroll
            for (int j = 0; j < 2; j++) {
                int idx = tid + j * 256;
                int hl  = idx >> 8;
                int rem = idx & 255;
                int row = rem >> 2;
                int c   = rem & 3;
                const __nv_bfloat16* src = (hl ? hlo : hhi)
                    + (size_t)row * HDIM + kglob + c * 8;
                uint32_t dst = smemu + RC_A_OFF(st, hl) + row * RC_SAS + c * 16;
                CP_ASYNC16(dst, src);
            }
            CP_COMMIT();
        };

        issueA(0);
#pragma unroll
        for (int kb = 0; kb < 8; kb++) {
            if (kb + 1 < 8) issueA(kb + 1);
            if (kb + 1 < 8) asm volatile("cp.async.wait_group 1;");
            else            asm volatile("cp.async.wait_group 0;");
            __syncthreads();

            int st = kb & 1;
#pragma unroll
            for (int kstep = 0; kstep < 2; kstep++) {
                uint32_t ah[2][4], al[2][4], bh[2][4], bl[2][4];
#pragma unroll
                for (int mt = 0; mt < 2; mt++) {
                    uint32_t base = smemu + (wm0 + mt * 16 + lrow) * RC_SAS
                                  + lhalf * 16 + kstep * 32;
                    LDSM4(ah[mt], base + RC_A_OFF(st, 0));
                    LDSM4(al[mt], base + RC_A_OFF(st, 1));
                }
                int klocal = kb * 32 + kstep * 16 + brow;
#pragma unroll
                for (int p = 0; p < 2; p++) {
                    uint32_t base = smemu + klocal * WH_STRIDE
                                  + (wn0 + p * 16 + bcolo) * 2;
                    LDSM4T(bh[p], base);
                    LDSM4T(bl[p], base + WH_HALF_BYTES);
                }
#pragma unroll
                for (int mt = 0; mt < 2; mt++)
#pragma unroll
                    for (int nt = 0; nt < 4; nt++) {
                        int p = nt >> 1, q = (nt & 1) * 2;
                        MMA_BF16(acc[mt][nt], ah[mt], bh[p][q], bh[p][q + 1]);
                        MMA_BF16(acc[mt][nt], ah[mt], bl[p][q], bl[p][q + 1]);
                        MMA_BF16(acc[mt][nt], al[mt], bh[p][q], bh[p][q + 1]);
                    }
            }
            __syncthreads();
        }

#pragma unroll
        for (int mt = 0; mt < 2; mt++) {
            int r0 = wm0 + mt * 16 + (lane >> 2);
            int r1 = r0 + 8;
#pragma unroll
            for (int nt = 0; nt < 4; nt++) {
                int n = nblk0 + wn0 + nt * 8 + (lane & 3) * 2;
                *(float2*)(g_part + ((size_t)(ksb * BATCH + r0) << 12) + n) =
                    make_float2(acc[mt][nt][0], acc[mt][nt][1]);
                *(float2*)(g_part + ((size_t)(ksb * BATCH + r1) << 12) + n) =
                    make_float2(acc[mt][nt][2], acc[mt][nt][3]);
            }
        }

        grid_barrier(++bar_epoch * NBLOCKS);

        {
            const float* xp = g_xproj + ((size_t)(t * BATCH + p2b) << 12);
            float2 v[4];
#pragma unroll
            for (int g = 0; g < 4; g++) {
                v[g] = *(const float2*)(xp + (g << 10) + p2hc);
#pragma unroll
                for (int ks = 0; ks < KSPLIT; ks++) {
                    float2 pv = *(const float2*)(g_part +
                        ((size_t)(ks * BATCH + p2b) << 12) + (g << 10) + p2hc);
                    v[g].x += pv.x;
                    v[g].y += pv.y;
                }
            }

            float2 cold = *(const float2*)(g_c + idx2);
            float2 hnew, cnew;
            {
                float i_t = 1.0f / (1.0f + expf(-v[0].x));
                float f_t = 1.0f / (1.0f + expf(-v[1].x));
                float gg  = tanhf(v[2].x);
                float o_t = 1.0f / (1.0f + expf(-v[3].x));
                cnew.x = f_t * cold.x + i_t * gg;
                hnew.x = o_t * tanhf(cnew.x);
            }
            {
                float i_t = 1.0f / (1.0f + expf(-v[0].y));
                float f_t = 1.0f / (1.0f + expf(-v[1].y));
                float gg  = tanhf(v[2].y);
                float o_t = 1.0f / (1.0f + expf(-v[3].y));
                cnew.y = f_t * cold.y + i_t * gg;
                hnew.y = o_t * tanhf(cnew.y);
            }

            *(float2*)(g_c + idx2) = cnew;
            if (t == TSTEPS - 1) {
                *(float2*)(out + idx2) = hnew;
                *(float2*)(out + BATCH * HDIM + idx2) = cnew;
            } else {
                __nv_bfloat16 h0 = __float2bfloat16(hnew.x);
                __nv_bfloat16 h1 = __float2bfloat16(hnew.y);
                __nv_bfloat16 l0 = __float2bfloat16(hnew.x - __bfloat162float(h0));
                __nv_bfloat16 l1 = __float2bfloat16(hnew.y - __bfloat162float(h1));
                __nv_bfloat162 hp; hp.x = h0; hp.y = h1;
                __nv_bfloat162 lp; lp.x = l0; lp.y = l1;
                *(__nv_bfloat162*)(&g_hhi[(t + 1) & 1][idx2]) = hp;
                *(__nv_bfloat162*)(&g_hlo[(t + 1) & 1][idx2]) = lp;
            }
        }

        if (t != TSTEPS - 1)
            grid_barrier(++bar_epoch * NBLOCKS);
    }
}

// ---------------- launch ----------------
extern "C" void kernel_launch(void* const* d_in, const int* in_sizes, int n_in,
                              void* d_out, int out_size)
{
    const float* x    = (const float*)d_in[0];
    const float* Wii  = (const float*)d_in[1];
    const float* Whi  = (const float*)d_in[2];
    const float* b_hi = (const float*)d_in[3];
    const float* Wif  = (const float*)d_in[4];
    const float* Whf  = (const float*)d_in[5];
    const float* b_hf = (const float*)d_in[6];
    const float* Wig  = (const float*)d_in[7];
    const float* Whg  = (const float*)d_in[8];
    const float* b_hg = (const float*)d_in[9];
    const float* Wio  = (const float*)d_in[10];
    const float* Who  = (const float*)d_in[11];
    const float* b_ho = (const float*)d_in[12];
    float* out = (float*)d_out;

    cudaFuncSetAttribute(xproj_tc2, cudaFuncAttributeMaxDynamicSharedMemorySize,
                         XQ_SMEM);
    cudaFuncSetAttribute(lstm_persistent_tc, cudaFuncAttributeMaxDynamicSharedMemorySize,
                         RC_SMEM_TOTAL);

    init_state<<<(BATCH * HDIM + 255) / 256, 256>>>();

    split_x<<<(int)(((size_t)BATCH * TSTEPS * IDIM / 2) / 256), 256>>>(x);
    split_w4<<<(int)(((size_t)IDIM * 4 * HDIM / 2) / 256), 256>>>(
        Wii, Wif, Wig, Wio, 0);
    split_w4<<<(int)(((size_t)HDIM * 4 * HDIM / 2) / 256), 256>>>(
        Whi, Whf, Whg, Who, 1);
    concat_bias<<<(4 * HDIM + 255) / 256, 256>>>(b_hi, b_hf, b_hg, b_ho);

    // m fastest: all blocks of a wave share one n-slice of Wx (L2-resident)
    xproj_tc2<<<dim3(BATCH * TSTEPS / 128, 4 * HDIM / 256), 512, XQ_SMEM>>>();

    lstm_persistent_tc<<<NBLOCKS, 256, RC_SMEM_TOTAL>>>(out);
}